// round 12
// baseline (speedup 1.0000x reference)
#include <cuda_runtime.h>
#include <cstdint>

// FlowNetC correlation: out[b, (dy+4)*9+(dx+4), y, x] =
//   (1/C) * sum_c in1[b,c,y,x] * in2[b,c,y+dy,x+dx], zero-padded.
// Shapes: in1,in2 [8,256,96,128] f32; out [8,81,96,128] f32.
//
// Block = TWO output rows (y0, y0+1); 288 threads = 9 warps; warp w <-> dy=w-4
// for BOTH rows. 10-row in2 window staged per channel chunk, shared by all
// warps; window row r holds in2 row y0+r-4 (clamped / zero-filled).
// Row y0   uses window row wid;  row y0+1 uses window row wid+1.
// in1 via LDG.128 (9 warps same addr -> L1 hits). 288 FMA per chunk per warp
// vs ~17 non-FMA -> ~94% FMA mix.

#define B_   8
#define C_   256
#define H_   96
#define W_   128
#define HW_  (H_ * W_)
#define CC   4            // channels per chunk
#define NDY  9            // dy values = warps per block
#define WR   10           // staged window rows (2 output rows + 8 halo)
#define W2   136          // padded in2 row: xx = x+4, x in [-4,131]
#define NTHR 288

typedef unsigned long long ull;

__device__ __forceinline__ void cp16(uint32_t sdst, ull gsrc, int srcsz) {
    asm volatile("cp.async.cg.shared.global [%0], [%1], 16, %2;"
                 :: "r"(sdst), "l"(gsrc), "r"(srcsz) : "memory");
}

__global__ __launch_bounds__(NTHR, 3) void corr_kernel(
    const float* __restrict__ in1,
    const float* __restrict__ in2,
    float* __restrict__ out)
{
    __shared__ float s2[2][CC][WR][W2];    // 43520 B

    const int y0   = blockIdx.x * 2;       // first output row
    const int b    = blockIdx.y;
    const int tid  = threadIdx.x;
    const int wid  = tid >> 5;             // dy index 0..8 (dy = wid-4)
    const int lane = tid & 31;
    const int x0   = lane << 2;            // 0..124

    // Zero the x-pads once (staging never writes xx<4 or xx>=132).
    if (tid < 2 * CC * WR) {
        float* row = &s2[0][0][0][0] + tid * W2;
#pragma unroll
        for (int j = 0; j < 4; j++) { row[j] = 0.0f; row[132 + j] = 0.0f; }
    }

    // ---- staging: warp w stages window row w (warp 0 also row 9). ----
    // window row r <- in2 row y0+r-4 (clamped; zero-filled via src_size=0).
    const int  r1    = wid;
    const int  y2a   = y0 + r1 - 4;
    const int  yca   = y2a < 0 ? 0 : (y2a > H_ - 1 ? H_ - 1 : y2a);
    const int  rszA  = ((unsigned)y2a < (unsigned)H_) ? 16 : 0;
    const bool two   = (wid == 0);         // warp 0 also stages row 9
    const int  y2b   = y0 + 5;             // window row 9 -> in2 row y0+5
    const int  ycb   = y2b > H_ - 1 ? H_ - 1 : y2b;
    const int  rszB  = (y2b < H_) ? 16 : 0;

    const ull gbase = (ull)__cvta_generic_to_global(
                          in2 + ((long)(b * C_)) * HW_) + (ull)x0 * 4u;
    ull srcA = gbase + (ull)yca * (W_ * 4);
    ull srcB = gbase + (ull)ycb * (W_ * 4);
    const uint32_t dstA =
        (uint32_t)__cvta_generic_to_shared(&s2[0][0][r1][4 + x0]);
    const uint32_t dstB =
        (uint32_t)__cvta_generic_to_shared(&s2[0][0][9][4 + x0]);
    const uint32_t CCB  = WR * W2 * 4;             // 5440  (cc stride)
    const uint32_t BUFB = CC * WR * W2 * 4;        // 21760 (buffer stride)
    const ull      HWB  = (ull)HW_ * 4u;

#define STAGE(bufsel)                                                         \
    {                                                                         \
        _Pragma("unroll")                                                     \
        for (int cc = 0; cc < CC; cc++) {                                     \
            cp16(dstA + (bufsel) * BUFB + cc * CCB, srcA + (ull)cc * HWB, rszA); \
            if (two)                                                          \
                cp16(dstB + (bufsel) * BUFB + cc * CCB, srcB + (ull)cc * HWB, rszB); \
        }                                                                     \
        asm volatile("cp.async.commit_group;" ::: "memory");                  \
        srcA += (ull)CC * HWB;                                                \
        srcB += (ull)CC * HWB;                                                \
    }

    // ---- prologue: chunk 0 -> buffer 0 ----
    STAGE(0u);
    asm volatile("cp.async.wait_group 0;" ::: "memory");
    __syncthreads();

    float acc0[NDY][4], acc1[NDY][4];      // [dx][px] for rows y0, y0+1
#pragma unroll
    for (int d = 0; d < NDY; d++)
#pragma unroll
        for (int i = 0; i < 4; i++) { acc0[d][i] = 0.0f; acc1[d][i] = 0.0f; }

    const float* a_run = in1 + ((long)(b * C_)) * HW_ + (long)y0 * W_ + x0;
    uint32_t buf = 0;

    for (int c0 = 0; c0 < C_; c0 += CC) {
        const bool has_next = (c0 + CC < C_);
        if (has_next) STAGE(buf ^ 1u);

#pragma unroll
        for (int cc = 0; cc < CC; cc++) {
            float4 a0 = *reinterpret_cast<const float4*>(a_run + (long)cc * HW_);
            float4 a1 = *reinterpret_cast<const float4*>(a_run + (long)cc * HW_ + W_);
            const float* sr0 = &s2[buf][cc][wid][x0];      // 16B aligned
            const float* sr1 = sr0 + W2;                   // window row wid+1
            float4 u0 = *reinterpret_cast<const float4*>(sr0);
            float4 u1 = *reinterpret_cast<const float4*>(sr0 + 4);
            float4 u2 = *reinterpret_cast<const float4*>(sr0 + 8);
            float4 v0 = *reinterpret_cast<const float4*>(sr1);
            float4 v1 = *reinterpret_cast<const float4*>(sr1 + 4);
            float4 v2 = *reinterpret_cast<const float4*>(sr1 + 8);
            float wu[12] = {u0.x, u0.y, u0.z, u0.w,
                            u1.x, u1.y, u1.z, u1.w,
                            u2.x, u2.y, u2.z, u2.w};
            float wv[12] = {v0.x, v0.y, v0.z, v0.w,
                            v1.x, v1.y, v1.z, v1.w,
                            v2.x, v2.y, v2.z, v2.w};
            float av0[4] = {a0.x, a0.y, a0.z, a0.w};
            float av1[4] = {a1.x, a1.y, a1.z, a1.w};
#pragma unroll
            for (int d = 0; d < NDY; d++)
#pragma unroll
                for (int i = 0; i < 4; i++) {
                    acc0[d][i] = fmaf(av0[i], wu[i + d], acc0[d][i]);
                    acc1[d][i] = fmaf(av1[i], wv[i + d], acc1[d][i]);
                }
        }
        a_run += (long)CC * HW_;

        if (has_next)
            asm volatile("cp.async.wait_group 0;" ::: "memory");
        __syncthreads();
        buf ^= 1u;
    }

    // ---- epilogue: 18 float4 stores (out channels wid*9 .. wid*9+8) ----
    const float sc = 1.0f / (float)C_;
    float* ob = out + (((long)b * 81 + wid * NDY) * H_ + y0) * (long)W_ + x0;
#pragma unroll
    for (int d = 0; d < NDY; d++) {
        float4 p = make_float4(acc0[d][0] * sc, acc0[d][1] * sc,
                               acc0[d][2] * sc, acc0[d][3] * sc);
        float4 q = make_float4(acc1[d][0] * sc, acc1[d][1] * sc,
                               acc1[d][2] * sc, acc1[d][3] * sc);
        *reinterpret_cast<float4*>(ob + (long)d * HW_)      = p;
        *reinterpret_cast<float4*>(ob + (long)d * HW_ + W_) = q;
    }
}

extern "C" void kernel_launch(void* const* d_in, const int* in_sizes, int n_in,
                              void* d_out, int out_size)
{
    const float* in1 = (const float*)d_in[0];
    const float* in2 = (const float*)d_in[1];
    float* out = (float*)d_out;

    dim3 grid(H_ / 2, B_);   // one block per (2 output rows, batch)
    dim3 block(NTHR);        // 9 warps: warp = dy, both rows
    corr_kernel<<<grid, block>>>(in1, in2, out);
}

// round 13
// speedup vs baseline: 4.7797x; 4.7797x over previous
#include <cuda_runtime.h>
#include <cstdint>

// FlowNetC correlation: out[b, (dy+4)*9+(dx+4), y, x] =
//   (1/C) * sum_c in1[b,c,y,x] * in2[b,c,y+dy,x+dx], zero-padded.
// Shapes: in1,in2 [8,256,96,128] f32; out [8,81,96,128] f32.
//
// Block = one output row (y0, b); 288 threads = 9 warps; warp w <-> dy=w-4.
// in2 9-row window staged per channel chunk (shared by all 9 dy-warps);
// in1 via LDG.128 (9 warps same addr -> L1 hits).
// R13: CC=8 (32 chunks -> half the barriers, 288 FMA between syncs) and
// launch_bounds(288,2) (reg cap 113 -> no spill; R12 spilled at cap 72).
// Dynamic smem (78336 B > 48KB static limit).

#define B_   8
#define C_   256
#define H_   96
#define W_   128
#define HW_  (H_ * W_)
#define CC   8            // channels per chunk (32 chunks)
#define NDY  9            // dy values = warps per block
#define W2   136          // padded in2 row: xx = x+4, x in [-4,131]
#define NTHR 288
#define SMEM_BYTES (2 * CC * NDY * W2 * 4)   // 78336

typedef unsigned long long ull;

__device__ __forceinline__ void cp16(uint32_t sdst, ull gsrc, int srcsz) {
    asm volatile("cp.async.cg.shared.global [%0], [%1], 16, %2;"
                 :: "r"(sdst), "l"(gsrc), "r"(srcsz) : "memory");
}

__global__ __launch_bounds__(NTHR, 2) void corr_kernel(
    const float* __restrict__ in1,
    const float* __restrict__ in2,
    float* __restrict__ out)
{
    extern __shared__ float s2[];          // [2][CC][NDY][W2]

    const int y0   = blockIdx.x;           // output row
    const int b    = blockIdx.y;
    const int tid  = threadIdx.x;
    const int wid  = tid >> 5;             // dy index 0..8 (dy = wid-4)
    const int lane = tid & 31;
    const int x0   = lane << 2;            // 0..124

    const uint32_t CCB  = NDY * W2;        // floats per cc slab
    const uint32_t BUFB = CC * CCB;        // floats per buffer

    // Zero the x-pads once (staging never writes xx<4 or xx>=132).
    if (tid < 2 * CC * NDY) {
        float* row = s2 + tid * W2;
#pragma unroll
        for (int j = 0; j < 4; j++) { row[j] = 0.0f; row[132 + j] = 0.0f; }
    }

    // ---- staging: warp wid stages window row wid (in2 row y0+wid-4,
    //      clamped; zero-filled via src_size=0), lane -> xx = 4+4*lane.
    const int  y2  = y0 + wid - 4;
    const int  yc  = y2 < 0 ? 0 : (y2 > H_ - 1 ? H_ - 1 : y2);
    const int  rsz = ((unsigned)y2 < (unsigned)H_) ? 16 : 0;
    ull st_run = (ull)__cvta_generic_to_global(
                     in2 + ((long)(b * C_)) * HW_ + (long)yc * W_ + x0);
    const uint32_t st_dst =
        (uint32_t)__cvta_generic_to_shared(&s2[(uint32_t)wid * W2 + 4 + x0]);
    const ull HWB = (ull)HW_ * 4u;

#define STAGE(bufsel)                                                         \
    {                                                                         \
        _Pragma("unroll")                                                     \
        for (int cc = 0; cc < CC; cc++)                                       \
            cp16(st_dst + ((bufsel) * BUFB + cc * CCB) * 4u,                  \
                 st_run + (ull)cc * HWB, rsz);                                \
        asm volatile("cp.async.commit_group;" ::: "memory");                  \
        st_run += (ull)CC * HWB;                                              \
    }

    // ---- prologue: chunk 0 -> buffer 0 ----
    STAGE(0u);
    asm volatile("cp.async.wait_group 0;" ::: "memory");
    __syncthreads();

    float acc[NDY][4];                     // [dx][px]
#pragma unroll
    for (int d = 0; d < NDY; d++)
#pragma unroll
        for (int i = 0; i < 4; i++) acc[d][i] = 0.0f;

    const float* a_run = in1 + ((long)(b * C_)) * HW_ + (long)y0 * W_ + x0;
    uint32_t buf = 0;

    for (int c0 = 0; c0 < C_; c0 += CC) {
        const bool has_next = (c0 + CC < C_);
        if (has_next) STAGE(buf ^ 1u);

        const float* sbase = s2 + buf * BUFB + (uint32_t)wid * W2 + x0;
#pragma unroll
        for (int cc = 0; cc < CC; cc++) {
            float4 a = *reinterpret_cast<const float4*>(a_run + (long)cc * HW_);
            const float* sr = sbase + cc * CCB;            // 16B aligned
            float4 w0 = *reinterpret_cast<const float4*>(sr);
            float4 w1 = *reinterpret_cast<const float4*>(sr + 4);
            float4 w2 = *reinterpret_cast<const float4*>(sr + 8);
            float wv[12] = {w0.x, w0.y, w0.z, w0.w,
                            w1.x, w1.y, w1.z, w1.w,
                            w2.x, w2.y, w2.z, w2.w};
            float av[4] = {a.x, a.y, a.z, a.w};
#pragma unroll
            for (int d = 0; d < NDY; d++)
#pragma unroll
                for (int i = 0; i < 4; i++)
                    acc[d][i] = fmaf(av[i], wv[i + d], acc[d][i]);
        }
        a_run += (long)CC * HW_;

        if (has_next)
            asm volatile("cp.async.wait_group 0;" ::: "memory");
        __syncthreads();
        buf ^= 1u;
    }

    // ---- epilogue: 9 float4 stores (out channels wid*9 .. wid*9+8) ----
    const float sc = 1.0f / (float)C_;
    float* ob = out + (((long)b * 81 + wid * NDY) * H_ + y0) * (long)W_ + x0;
#pragma unroll
    for (int d = 0; d < NDY; d++) {
        float4 v = make_float4(acc[d][0] * sc, acc[d][1] * sc,
                               acc[d][2] * sc, acc[d][3] * sc);
        *reinterpret_cast<float4*>(ob + (long)d * HW_) = v;
    }
}

extern "C" void kernel_launch(void* const* d_in, const int* in_sizes, int n_in,
                              void* d_out, int out_size)
{
    const float* in1 = (const float*)d_in[0];
    const float* in2 = (const float*)d_in[1];
    float* out = (float*)d_out;

    cudaFuncSetAttribute(corr_kernel,
                         cudaFuncAttributeMaxDynamicSharedMemorySize,
                         SMEM_BYTES);

    dim3 grid(H_, B_);     // one block per (output row, batch)
    dim3 block(NTHR);      // 9 warps: warp = dy
    corr_kernel<<<grid, block, SMEM_BYTES>>>(in1, in2, out);
}

// round 14
// speedup vs baseline: 6.3541x; 1.3294x over previous
#include <cuda_runtime.h>
#include <cstdint>

// FlowNetC correlation: out[b, (dy+4)*9+(dx+4), y, x] =
//   (1/C) * sum_c in1[b,c,y,x] * in2[b,c,y+dy,x+dx], zero-padded.
// Shapes: in1,in2 [8,256,96,128] f32; out [8,81,96,128] f32.
//
// Frame = R4 (best, 166.6us): block = one dy x 8 rows x batch, 256 thr,
// warp = row, lane -> 4 consecutive x; in2 rows staged with cp.async into
// a double-buffered window; in1 via LDG.128.
// R14 change: warp w stages exactly (and only) the row warp w consumes, so
// the per-chunk __syncthreads() pairs are pure overhead -> replaced with
// per-warp cp.async.wait_group + __syncwarp(). Warps become independent
// pipelines: no block barriers, no cross-warp convoy on staging latency.

#define B_   8
#define C_   256
#define H_   96
#define W_   128
#define HW_  (H_ * W_)
#define CC   4      // channels per chunk
#define ROWS 8      // output rows per block (warp = row)
#define W2   136    // padded in2 row: xx = x + 4, x in [-4, 131]

typedef unsigned long long ull;

__device__ __forceinline__ void cp16(uint32_t sdst, ull gsrc, int srcsz) {
    asm volatile("cp.async.cg.shared.global [%0], [%1], 16, %2;"
                 :: "r"(sdst), "l"(gsrc), "r"(srcsz) : "memory");
}

__global__ __launch_bounds__(256, 3) void corr_kernel(
    const float* __restrict__ in1,
    const float* __restrict__ in2,
    float* __restrict__ out)
{
    __shared__ float s2[2][CC][ROWS][W2];   // 34816 B

    const int dyi  = blockIdx.x;        // 0..8
    const int y0   = blockIdx.y * ROWS;
    const int b    = blockIdx.z;
    const int tid  = threadIdx.x;
    const int wid  = tid >> 5;          // warp = row, 0..7
    const int lane = tid & 31;
    const int x0   = lane << 2;         // 0..124
    const int dyo  = dyi - 4;

    // Warp-local pad zeroing: warp w zeros the x-pads of ITS row w in both
    // buffers and all cc (2*CC*8 = 64 floats; lanes 0..31 take 2 each).
    {
        int k = lane;                   // 0..31 -> (buf,cc,side) combos
#pragma unroll
        for (int rep = 0; rep < 2; rep++, k += 32) {
            int bufcc = k >> 3;         // 0..7  = buf*CC + cc
            int j     = k & 7;          // 0..7  = pad float index
            int xx    = (j < 4) ? j : (128 + j);   // 0..3 or 132..135
            s2[bufcc >> 2][bufcc & 3][wid][xx] = 0.0f;
        }
    }

    // ---- staging: warp wid stages in2 row y0+wid+dyo (clamped; zero-filled
    //      via src_size=0 when out of range), lane -> xx = 4+4*lane. This is
    //      exactly the row ONLY warp wid consumes -> warp-local pipeline.
    const int  y2    = y0 + wid + dyo;
    const bool valid = ((unsigned)y2 < (unsigned)H_);
    const int  srcsz = valid ? 16 : 0;
    ull st_run = (ull)__cvta_generic_to_global(
                     in2 + ((long)(b * C_)) * HW_
                         + (long)(valid ? y2 : 0) * W_ + x0);
    const uint32_t st_dst =
        (uint32_t)__cvta_generic_to_shared(&s2[0][0][wid][4 + x0]);
    const uint32_t CCB  = ROWS * W2 * 4;          // 4352  (cc stride, bytes)
    const uint32_t BUFB = CC * ROWS * W2 * 4;     // 17408 (buffer stride)
    const ull      HWB  = (ull)HW_ * 4u;

#define STAGE(bufsel)                                                         \
    {                                                                         \
        _Pragma("unroll")                                                     \
        for (int cc = 0; cc < CC; cc++)                                       \
            cp16(st_dst + (bufsel) * BUFB + cc * CCB,                         \
                 st_run + (ull)cc * HWB, srcsz);                              \
        asm volatile("cp.async.commit_group;" ::: "memory");                  \
        st_run += (ull)CC * HWB;                                              \
    }

    // ---- prologue: chunk 0 -> buffer 0 (warp-local sync only) ----
    STAGE(0u);
    asm volatile("cp.async.wait_group 0;" ::: "memory");
    __syncwarp();

    float acc[4][9];
#pragma unroll
    for (int i = 0; i < 4; i++)
#pragma unroll
        for (int d = 0; d < 9; d++) acc[i][d] = 0.0f;

    const float* a_run = in1 + ((long)(b * C_)) * HW_
                             + (long)(y0 + wid) * W_ + x0;
    uint32_t buf = 0;

    for (int c0 = 0; c0 < C_; c0 += CC) {
        const bool has_next = (c0 + CC < C_);
        if (has_next) STAGE(buf ^ 1u);

        // Compute on current buffer (overlaps the async copies above).
#pragma unroll
        for (int cc = 0; cc < CC; cc++) {
            float4 a = *reinterpret_cast<const float4*>(a_run + (long)cc * HW_);
            const float* sr = &s2[buf][cc][wid][x0];       // 16B aligned
            float4 w0 = *reinterpret_cast<const float4*>(sr);
            float4 w1 = *reinterpret_cast<const float4*>(sr + 4);
            float4 w2 = *reinterpret_cast<const float4*>(sr + 8);
            float w[12] = {w0.x, w0.y, w0.z, w0.w,
                           w1.x, w1.y, w1.z, w1.w,
                           w2.x, w2.y, w2.z, w2.w};
            float av[4] = {a.x, a.y, a.z, a.w};
#pragma unroll
            for (int i = 0; i < 4; i++)
#pragma unroll
                for (int d = 0; d < 9; d++)
                    acc[i][d] = fmaf(av[i], w[i + d], acc[i][d]);
        }
        a_run += (long)CC * HW_;

        if (has_next)
            asm volatile("cp.async.wait_group 0;" ::: "memory");
        __syncwarp();          // warp-local: order staged data vs next reads
        buf ^= 1u;
    }

    // ---- epilogue: 9 float4 stores per thread ----
    const float sc = 1.0f / (float)C_;
    float* ob = out + (((long)b * 81 + dyi * 9) * H_ + (y0 + wid)) * (long)W_ + x0;
#pragma unroll
    for (int d = 0; d < 9; d++) {
        float4 v = make_float4(acc[0][d] * sc, acc[1][d] * sc,
                               acc[2][d] * sc, acc[3][d] * sc);
        *reinterpret_cast<float4*>(ob + (long)d * HW_) = v;
    }
}

extern "C" void kernel_launch(void* const* d_in, const int* in_sizes, int n_in,
                              void* d_out, int out_size)
{
    const float* in1 = (const float*)d_in[0];
    const float* in2 = (const float*)d_in[1];
    float* out = (float*)d_out;

    dim3 grid(9, H_ / ROWS, B_);   // dy, y-tiles, batch
    dim3 block(256);
    corr_kernel<<<grid, block>>>(in1, in2, out);
}

// round 15
// speedup vs baseline: 6.3555x; 1.0002x over previous
#include <cuda_runtime.h>
#include <cstdint>

// FlowNetC correlation: out[b, (dy+4)*9+(dx+4), y, x] =
//   (1/C) * sum_c in1[b,c,y,x] * in2[b,c,y+dy,x+dx], zero-padded.
// Shapes: in1,in2 [8,256,96,128] f32; out [8,81,96,128] f32.
//
// Frame = R14 (warp-local pipelines, no block barriers) reorganized to
// 3 dy per block: 12 warps = (dyl 0..2) x (row 0..3), 384 threads.
// Each warp: private acc[4][9], stages its own in2 row via cp.async
// (duplicates tolerated -> in2 traffic unchanged), __syncwarp only.
// Gain: warps with same row, different dyl read IDENTICAL in1 addresses
// -> 2/3 of in1 LDGs hit L1, in1 L2 traffic /3.

#define B_   8
#define C_   256
#define H_   96
#define W_   128
#define HW_  (H_ * W_)
#define CC   4      // channels per chunk
#define NW   12     // warps per block = 3 dy x 4 rows
#define RWS  4      // output rows per block
#define W2   136    // padded in2 row: xx = x + 4, x in [-4, 131]
#define SMEM_BYTES (2 * CC * NW * W2 * 4)   // 52224

typedef unsigned long long ull;

__device__ __forceinline__ void cp16(uint32_t sdst, ull gsrc, int srcsz) {
    asm volatile("cp.async.cg.shared.global [%0], [%1], 16, %2;"
                 :: "r"(sdst), "l"(gsrc), "r"(srcsz) : "memory");
}

__global__ __launch_bounds__(384, 2) void corr_kernel(
    const float* __restrict__ in1,
    const float* __restrict__ in2,
    float* __restrict__ out)
{
    extern __shared__ float s2[];       // [2][CC][NW][W2]

    const int dygrp = blockIdx.x;       // 0..2 -> dy = 3*dygrp + dyl - 4
    const int y0    = blockIdx.y * RWS;
    const int b     = blockIdx.z;
    const int tid   = threadIdx.x;
    const int wid   = tid >> 5;         // 0..11
    const int lane  = tid & 31;
    const int dyl   = wid >> 2;         // 0..2
    const int row   = wid & 3;          // 0..3
    const int x0    = lane << 2;        // 0..124
    const int dyo   = 3 * dygrp + dyl - 4;

    // Warp-local pad zeroing: warp w zeros x-pads of ITS slot w in both
    // buffers, all cc (2*CC = 8 combos x 8 pad floats; lanes take 2 each).
    {
        int k = lane;
#pragma unroll
        for (int rep = 0; rep < 2; rep++, k += 32) {
            int bufcc = k >> 3;         // 0..7 = buf*CC + cc
            int j     = k & 7;          // 0..7
            int xx    = (j < 4) ? j : (128 + j);   // 0..3 or 132..135
            s2[((uint32_t)bufcc * NW + wid) * W2 + xx] = 0.0f;
        }
    }

    // ---- staging: warp stages in2 row y0+row+dyo (clamped; zero-filled
    //      via src_size=0 when out of range), lane -> xx = 4+4*lane.
    const int  y2    = y0 + row + dyo;
    const bool valid = ((unsigned)y2 < (unsigned)H_);
    const int  srcsz = valid ? 16 : 0;
    ull st_run = (ull)__cvta_generic_to_global(
                     in2 + ((long)(b * C_)) * HW_
                         + (long)(valid ? y2 : 0) * W_ + x0);
    const uint32_t st_dst = (uint32_t)__cvta_generic_to_shared(
                                &s2[(uint32_t)wid * W2 + 4 + x0]);
    const uint32_t CCB  = NW * W2 * 4;            // 6528  (cc stride, bytes)
    const uint32_t BUFB = CC * NW * W2 * 4;       // 26112 (buffer stride)
    const ull      HWB  = (ull)HW_ * 4u;

#define STAGE(bufsel)                                                         \
    {                                                                         \
        _Pragma("unroll")                                                     \
        for (int cc = 0; cc < CC; cc++)                                       \
            cp16(st_dst + (bufsel) * BUFB + cc * CCB,                         \
                 st_run + (ull)cc * HWB, srcsz);                              \
        asm volatile("cp.async.commit_group;" ::: "memory");                  \
        st_run += (ull)CC * HWB;                                              \
    }

    // ---- prologue: chunk 0 -> buffer 0 (warp-local sync only) ----
    STAGE(0u);
    asm volatile("cp.async.wait_group 0;" ::: "memory");
    __syncwarp();

    float acc[4][9];
#pragma unroll
    for (int i = 0; i < 4; i++)
#pragma unroll
        for (int d = 0; d < 9; d++) acc[i][d] = 0.0f;

    const float* a_run = in1 + ((long)(b * C_)) * HW_
                             + (long)(y0 + row) * W_ + x0;
    uint32_t buf = 0;

    for (int c0 = 0; c0 < C_; c0 += CC) {
        const bool has_next = (c0 + CC < C_);
        if (has_next) STAGE(buf ^ 1u);

#pragma unroll
        for (int cc = 0; cc < CC; cc++) {
            float4 a = *reinterpret_cast<const float4*>(a_run + (long)cc * HW_);
            const float* sr = s2 + (((uint32_t)buf * CC + cc) * NW + wid) * W2 + x0;
            float4 w0 = *reinterpret_cast<const float4*>(sr);
            float4 w1 = *reinterpret_cast<const float4*>(sr + 4);
            float4 w2 = *reinterpret_cast<const float4*>(sr + 8);
            float w[12] = {w0.x, w0.y, w0.z, w0.w,
                           w1.x, w1.y, w1.z, w1.w,
                           w2.x, w2.y, w2.z, w2.w};
            float av[4] = {a.x, a.y, a.z, a.w};
#pragma unroll
            for (int i = 0; i < 4; i++)
#pragma unroll
                for (int d = 0; d < 9; d++)
                    acc[i][d] = fmaf(av[i], w[i + d], acc[i][d]);
        }
        a_run += (long)CC * HW_;

        if (has_next)
            asm volatile("cp.async.wait_group 0;" ::: "memory");
        __syncwarp();
        buf ^= 1u;
    }

    // ---- epilogue: 9 float4 stores per thread ----
    const float sc = 1.0f / (float)C_;
    const int dyi = 3 * dygrp + dyl;   // 0..8
    float* ob = out + (((long)b * 81 + dyi * 9) * H_ + (y0 + row)) * (long)W_ + x0;
#pragma unroll
    for (int d = 0; d < 9; d++) {
        float4 v = make_float4(acc[0][d] * sc, acc[1][d] * sc,
                               acc[2][d] * sc, acc[3][d] * sc);
        *reinterpret_cast<float4*>(ob + (long)d * HW_) = v;
    }
}

extern "C" void kernel_launch(void* const* d_in, const int* in_sizes, int n_in,
                              void* d_out, int out_size)
{
    const float* in1 = (const float*)d_in[0];
    const float* in2 = (const float*)d_in[1];
    float* out = (float*)d_out;

    cudaFuncSetAttribute(corr_kernel,
                         cudaFuncAttributeMaxDynamicSharedMemorySize,
                         SMEM_BYTES);

    dim3 grid(3, H_ / RWS, B_);   // dy-group, y-tiles, batch
    dim3 block(384);              // 12 warps = 3 dy x 4 rows
    corr_kernel<<<grid, block, SMEM_BYTES>>>(in1, in2, out);
}